// round 1
// baseline (speedup 1.0000x reference)
#include <cuda_runtime.h>
#include <cstdint>
#include <cstdio>

// ---------------------------------------------------------------------------
// PointNet++ (3 SA stages) forward for B=64, N=4096 input, fp32.
// Stages: (npoint, radius, nsample) = (128,0.02,32), (64,0.04,32), (32,0.08,16)
// Layers: 9->32->64, 67->128->128, 131->256->256 (conv1x1 + folded BN + relu)
// Output: (64, 256, 32) float32.
// ---------------------------------------------------------------------------

static constexpr int B   = 64;
static constexpr int N0  = 4096;
static constexpr int S0  = 128, NSAMP0 = 32;
static constexpr int S1  = 64,  NSAMP1 = 32;
static constexpr int S2  = 32,  NSAMP2 = 16;

// ------------------------- device scratch (no allocs) ----------------------
__device__ float g_nx1[B * S0 * 3];
__device__ float g_nx2[B * S1 * 3];
__device__ float g_nx3[B * S2 * 3];
__device__ int   g_idxbuf[B * S0 * NSAMP0];      // reused by all stages (max size)
__device__ float g_f1[B * S0 * 64];              // stage0 out feats, (B,S0,64)
__device__ float g_f2[B * S1 * 128];             // stage1 out feats, (B,S1,128)

__device__ float g_w0T[9 * 32];     __device__ float g_b0[32];
__device__ float g_w1T[32 * 64];    __device__ float g_b1[64];
__device__ float g_w2T[67 * 128];   __device__ float g_b2[128];
__device__ float g_w3T[128 * 128];  __device__ float g_b3[128];
__device__ float g_w4T[131 * 256];  __device__ float g_b4[256];
__device__ float g_w5T[256 * 256];  __device__ float g_b5[256];

// ------------------------- BN fold: wT[k*Cout+o] = w[o,k]*s, b' = be - s*m --
__global__ void fold_kernel(const float* __restrict__ w,  const float* __restrict__ g,
                            const float* __restrict__ be, const float* __restrict__ rm,
                            const float* __restrict__ rv,
                            float* __restrict__ wT, float* __restrict__ bias,
                            int Cin, int Cout)
{
    int i = blockIdx.x * blockDim.x + threadIdx.x;
    int tot = Cin * Cout;
    if (i < Cout) {
        float s = g[i] * rsqrtf(rv[i] + 1e-5f);
        bias[i] = be[i] - s * rm[i];
    }
    for (int e = i; e < tot; e += gridDim.x * blockDim.x) {
        int o = e / Cin, k = e - o * Cin;
        float s = g[o] * rsqrtf(rv[o] + 1e-5f);
        wT[k * Cout + o] = w[e] * s;
    }
}

// ------------------------- farthest point sampling -------------------------
// One block per batch. Points & running min-dist live in registers.
// Matches jnp.argmax first-max tie semantics via (value, index) lexicographic
// reduce; distance math uses non-fused fp32 ops to match XLA exactly.
template<int N, int NPOINT, int T>
__global__ void __launch_bounds__(T) fps_kernel(const float* __restrict__ xyz,
                                                float* __restrict__ newxyz)
{
    constexpr int PPT = N / T;
    int b = blockIdx.x;
    int tid = threadIdx.x;
    const float* x = xyz + (size_t)b * N * 3;

    float px[PPT], py[PPT], pz[PPT], dist[PPT];
#pragma unroll
    for (int i = 0; i < PPT; i++) {
        int p = tid + i * T;
        px[i] = x[p * 3 + 0];
        py[i] = x[p * 3 + 1];
        pz[i] = x[p * 3 + 2];
        dist[i] = 1e10f;
    }

    __shared__ float cur[3];
    __shared__ float wv[T / 32];
    __shared__ int   wi[T / 32];

    if (tid == 0) {
        cur[0] = x[0]; cur[1] = x[1]; cur[2] = x[2];
        float* o = newxyz + (size_t)b * NPOINT * 3;
        o[0] = x[0]; o[1] = x[1]; o[2] = x[2];
    }
    __syncthreads();

    for (int j = 1; j < NPOINT; j++) {
        float cx = cur[0], cy = cur[1], cz = cur[2];
        float bv = -1.0f;
        int   bi = 0x7fffffff;
#pragma unroll
        for (int i = 0; i < PPT; i++) {
            float dx = px[i] - cx, dy = py[i] - cy, dz = pz[i] - cz;
            float d = __fadd_rn(__fadd_rn(__fmul_rn(dx, dx), __fmul_rn(dy, dy)),
                                __fmul_rn(dz, dz));
            float nd = fminf(dist[i], d);
            dist[i] = nd;
            int gidx = tid + i * T;
            if (nd > bv || (nd == bv && gidx < bi)) { bv = nd; bi = gidx; }
        }
        // intra-warp argmax
#pragma unroll
        for (int off = 16; off > 0; off >>= 1) {
            float ov = __shfl_down_sync(0xffffffffu, bv, off);
            int   oi = __shfl_down_sync(0xffffffffu, bi, off);
            if (ov > bv || (ov == bv && oi < bi)) { bv = ov; bi = oi; }
        }
        if ((tid & 31) == 0) { wv[tid >> 5] = bv; wi[tid >> 5] = bi; }
        __syncthreads();
        if (tid < 32) {
            constexpr int NW = T / 32;
            bv = (tid < NW) ? wv[tid] : -2.0f;
            bi = (tid < NW) ? wi[tid] : 0x7fffffff;
#pragma unroll
            for (int off = 16; off > 0; off >>= 1) {
                float ov = __shfl_down_sync(0xffffffffu, bv, off);
                int   oi = __shfl_down_sync(0xffffffffu, bi, off);
                if (ov > bv || (ov == bv && oi < bi)) { bv = ov; bi = oi; }
            }
            if (tid == 0) {
                const float* p = x + (size_t)bi * 3;
                float nx = p[0], ny = p[1], nz = p[2];
                cur[0] = nx; cur[1] = ny; cur[2] = nz;
                float* o = newxyz + ((size_t)b * NPOINT + j) * 3;
                o[0] = nx; o[1] = ny; o[2] = nz;
            }
        }
        __syncthreads();
    }
}

// ------------------------- ball query --------------------------------------
// One warp per query. Collects the first NS indices (ascending) with d2 < rr,
// pads with the first hit. Matches sort-of-sentinels reference semantics.
template<int NS>
__global__ void ballquery_kernel(const float* __restrict__ newxyz,
                                 const float* __restrict__ xyz,
                                 int* __restrict__ idxout,
                                 int N, int S, float rr)
{
    __shared__ int rows[4][NS];
    int lane = threadIdx.x & 31;
    int wip  = threadIdx.x >> 5;
    int q = blockIdx.x * 4 + wip;               // query id in [0, B*S)
    int b = q / S;
    const float* nq = newxyz + (size_t)q * 3;
    float qx = nq[0], qy = nq[1], qz = nq[2];
    const float* x = xyz + (size_t)b * N * 3;
    int* row = rows[wip];
    int cnt = 0;

    for (int base = 0; base < N; base += 32) {
        if (cnt >= NS) break;
        int p = base + lane;
        float dx = x[p * 3 + 0] - qx;
        float dy = x[p * 3 + 1] - qy;
        float dz = x[p * 3 + 2] - qz;
        float d = __fadd_rn(__fadd_rn(__fmul_rn(dx, dx), __fmul_rn(dy, dy)),
                            __fmul_rn(dz, dz));
        bool hit = d < rr;
        unsigned m = __ballot_sync(0xffffffffu, hit);
        if (hit) {
            int pos = cnt + __popc(m & ((1u << lane) - 1u));
            if (pos < NS) row[pos] = p;
        }
        cnt += __popc(m);
    }
    __syncwarp();
    int first = (cnt > 0) ? row[0] : 0;
    for (int t = cnt + lane; t < NS; t += 32) row[t] = first;
    __syncwarp();
    for (int t = lane; t < NS; t += 32) idxout[(size_t)q * NS + t] = row[t];
}

// ------------------------- fused group + MLP(2) + maxpool ------------------
// One block per (batch, centroid). Gathers the group into smem, runs two
// 1x1-conv layers (BN folded, relu), max-pools over the samples.
// Thread t = output channel; acc[NS] in registers; smem rows read as float4
// broadcasts (conflict-free).
template<int CIN, int C0, int C1, int NS, int T, bool STAGE0, bool FINAL>
__global__ void __launch_bounds__(T) sa_mlp_kernel(
    const float* __restrict__ xyz, const float* __restrict__ feats,
    const float* __restrict__ newxyz, const int* __restrict__ idx,
    const float* __restrict__ w0T, const float* __restrict__ b0,
    const float* __restrict__ w1T, const float* __restrict__ b1,
    float* __restrict__ out, int N, int S)
{
    constexpr int LD = NS + 4;                  // pad: conflict-light, 16B aligned
    __shared__ __align__(16) float xs[CIN * LD];
    __shared__ __align__(16) float mid[C0 * LD];

    int gs = blockIdx.x;
    int b = gs / S, s = gs - b * S;
    int tid = threadIdx.x;
    const int* gi = idx + (size_t)gs * NS;
    float cx = newxyz[gs * 3 + 0], cy = newxyz[gs * 3 + 1], cz = newxyz[gs * 3 + 2];

    // gather xyz-relative rows (+ absolute xyz duplicated for stage0 feats)
    for (int n = tid; n < NS; n += T) {
        int id = gi[n];
        const float* p = xyz + ((size_t)b * N + id) * 3;
        float ax = p[0], ay = p[1], az = p[2];
        xs[0 * LD + n] = ax - cx;
        xs[1 * LD + n] = ay - cy;
        xs[2 * LD + n] = az - cz;
        if (STAGE0) {
            xs[3 * LD + n] = ax; xs[4 * LD + n] = ay; xs[5 * LD + n] = az;
            xs[6 * LD + n] = ax; xs[7 * LD + n] = ay; xs[8 * LD + n] = az;
        }
    }
    if constexpr (!STAGE0) {
        constexpr int CF = CIN - 3;
        for (int e = tid; e < CF * NS; e += T) {
            int n = e / CF, c = e - n * CF;
            xs[(3 + c) * LD + n] = feats[((size_t)b * N + gi[n]) * CF + c];
        }
    }
    __syncthreads();

    // layer 0
    if (tid < C0) {
        float acc[NS];
        float bb = b0[tid];
#pragma unroll
        for (int n = 0; n < NS; n++) acc[n] = bb;
#pragma unroll 4
        for (int k = 0; k < CIN; k++) {
            float w = w0T[k * C0 + tid];
            const float4* xr = reinterpret_cast<const float4*>(&xs[k * LD]);
#pragma unroll
            for (int j = 0; j < NS / 4; j++) {
                float4 v = xr[j];
                acc[4 * j + 0] = fmaf(w, v.x, acc[4 * j + 0]);
                acc[4 * j + 1] = fmaf(w, v.y, acc[4 * j + 1]);
                acc[4 * j + 2] = fmaf(w, v.z, acc[4 * j + 2]);
                acc[4 * j + 3] = fmaf(w, v.w, acc[4 * j + 3]);
            }
        }
#pragma unroll
        for (int n = 0; n < NS; n++) mid[tid * LD + n] = fmaxf(acc[n], 0.0f);
    }
    __syncthreads();

    // layer 1 + maxpool
    if (tid < C1) {
        float acc[NS];
        float bb = b1[tid];
#pragma unroll
        for (int n = 0; n < NS; n++) acc[n] = bb;
#pragma unroll 4
        for (int k = 0; k < C0; k++) {
            float w = w1T[k * C1 + tid];
            const float4* mr = reinterpret_cast<const float4*>(&mid[k * LD]);
#pragma unroll
            for (int j = 0; j < NS / 4; j++) {
                float4 v = mr[j];
                acc[4 * j + 0] = fmaf(w, v.x, acc[4 * j + 0]);
                acc[4 * j + 1] = fmaf(w, v.y, acc[4 * j + 1]);
                acc[4 * j + 2] = fmaf(w, v.z, acc[4 * j + 2]);
                acc[4 * j + 3] = fmaf(w, v.w, acc[4 * j + 3]);
            }
        }
        float mx = acc[0];
#pragma unroll
        for (int n = 1; n < NS; n++) mx = fmaxf(mx, acc[n]);
        mx = fmaxf(mx, 0.0f);
        if (FINAL)
            out[(size_t)b * C1 * S + (size_t)tid * S + s] = mx;   // (B, C, S)
        else
            out[((size_t)b * S + s) * C1 + tid] = mx;             // (B, S, C)
    }
}

// ---------------------------------------------------------------------------
extern "C" void kernel_launch(void* const* d_in, const int* in_sizes, int n_in,
                              void* d_out, int out_size)
{
    (void)in_sizes; (void)n_in; (void)out_size;
    const float* pc = (const float*)d_in[0];
    const float *W[6], *G[6], *BE[6], *RM[6], *RV[6];
    for (int l = 0; l < 6; l++) {
        W[l]  = (const float*)d_in[1 + 5 * l];
        G[l]  = (const float*)d_in[2 + 5 * l];
        BE[l] = (const float*)d_in[3 + 5 * l];
        RM[l] = (const float*)d_in[4 + 5 * l];
        RV[l] = (const float*)d_in[5 + 5 * l];
    }

    float *nx1, *nx2, *nx3, *f1, *f2;
    int* idxb;
    float *w0T, *w1T, *w2T, *w3T, *w4T, *w5T;
    float *b0, *b1, *b2, *b3, *b4, *b5;
    cudaGetSymbolAddress((void**)&nx1, g_nx1);
    cudaGetSymbolAddress((void**)&nx2, g_nx2);
    cudaGetSymbolAddress((void**)&nx3, g_nx3);
    cudaGetSymbolAddress((void**)&idxb, g_idxbuf);
    cudaGetSymbolAddress((void**)&f1, g_f1);
    cudaGetSymbolAddress((void**)&f2, g_f2);
    cudaGetSymbolAddress((void**)&w0T, g_w0T); cudaGetSymbolAddress((void**)&b0, g_b0);
    cudaGetSymbolAddress((void**)&w1T, g_w1T); cudaGetSymbolAddress((void**)&b1, g_b1);
    cudaGetSymbolAddress((void**)&w2T, g_w2T); cudaGetSymbolAddress((void**)&b2, g_b2);
    cudaGetSymbolAddress((void**)&w3T, g_w3T); cudaGetSymbolAddress((void**)&b3, g_b3);
    cudaGetSymbolAddress((void**)&w4T, g_w4T); cudaGetSymbolAddress((void**)&b4, g_b4);
    cudaGetSymbolAddress((void**)&w5T, g_w5T); cudaGetSymbolAddress((void**)&b5, g_b5);

    const int cins[6]  = {9, 32, 67, 128, 131, 256};
    const int couts[6] = {32, 64, 128, 128, 256, 256};
    float* wTs[6] = {w0T, w1T, w2T, w3T, w4T, w5T};
    float* bsx[6] = {b0, b1, b2, b3, b4, b5};
    for (int l = 0; l < 6; l++) {
        int tot = cins[l] * couts[l];
        int grid = (tot + 255) / 256;
        fold_kernel<<<grid, 256>>>(W[l], G[l], BE[l], RM[l], RV[l],
                                   wTs[l], bsx[l], cins[l], couts[l]);
    }

    const float rr0 = (float)(0.02 * 0.02);
    const float rr1 = (float)(0.04 * 0.04);
    const float rr2 = (float)(0.08 * 0.08);

    // ---- stage 0: N=4096 -> S=128 ----
    fps_kernel<4096, 128, 256><<<B, 256>>>(pc, nx1);
    ballquery_kernel<32><<<(B * S0) / 4, 128>>>(nx1, pc, idxb, N0, S0, rr0);
    sa_mlp_kernel<9, 32, 64, 32, 64, true, false><<<B * S0, 64>>>(
        pc, nullptr, nx1, idxb, w0T, b0, w1T, b1, f1, N0, S0);

    // ---- stage 1: N=128 -> S=64 ----
    fps_kernel<128, 64, 128><<<B, 128>>>(nx1, nx2);
    ballquery_kernel<32><<<(B * S1) / 4, 128>>>(nx2, nx1, idxb, S0, S1, rr1);
    sa_mlp_kernel<67, 128, 128, 32, 128, false, false><<<B * S1, 128>>>(
        nx1, f1, nx2, idxb, w2T, b2, w3T, b3, f2, S0, S1);

    // ---- stage 2: N=64 -> S=32 ----
    fps_kernel<64, 32, 64><<<B, 64>>>(nx2, nx3);
    ballquery_kernel<16><<<(B * S2) / 4, 128>>>(nx3, nx2, idxb, S1, S2, rr2);
    sa_mlp_kernel<131, 256, 256, 16, 256, false, true><<<B * S2, 256>>>(
        nx2, f2, nx3, idxb, w4T, b4, w5T, b5, (float*)d_out, S1, S2);
}